// round 1
// baseline (speedup 1.0000x reference)
#include <cuda_runtime.h>
#include <cstdint>

typedef unsigned long long u64;

__device__ __forceinline__ u64 ffma2(u64 a, u64 b, u64 c) {
    u64 d;
    asm("fma.rn.f32x2 %0, %1, %2, %3;" : "=l"(d) : "l"(a), "l"(b), "l"(c));
    return d;
}
__device__ __forceinline__ u64 dup2(float x) {
    u64 d;
    unsigned u = __float_as_uint(x);
    asm("mov.b64 %0, {%1, %1};" : "=l"(d) : "r"(u));
    return d;
}
__device__ __forceinline__ float lo2(u64 v) { return __uint_as_float((unsigned)v); }
__device__ __forceinline__ float hi2(u64 v) { return __uint_as_float((unsigned)(v >> 32)); }

#define NB    16
#define TT    8
#define LL    197
#define HH    12
#define DD    64
#define LK    196
#define NPAIR 112
#define CDIM  768

// attn scratch: [half][q][pair][k]  = 2*196*112*196 floats = 34.4 MB
__device__ float g_attn[2u * LK * NPAIR * LK];

// ---------------------------------------------------------------------------
// Kernel 1: fused scores + softmax + mean over heads
// grid (7 qtiles, 112 pairs, 2 halves), 224 threads
// thread (qi = tid>>3 in [0,28), kg = tid&7) owns q = q0+qi, k = kg + 8*j
// ---------------------------------------------------------------------------
#define QT 28
#define K1_THREADS 224
#define ROWP 68
#define SMEM1 ((QT + 200) * ROWP * 4)

__global__ void __launch_bounds__(K1_THREADS) attn_kernel(
    const float* __restrict__ q, const float* __restrict__ k)
{
    extern __shared__ float sm[];
    float* qs = sm;               // [QT][ROWP]
    float* ks = sm + QT * ROWP;   // [200][ROWP] (rows 196..199 unused/garbage, masked)

    const int qt   = blockIdx.x;
    const int p    = blockIdx.y;
    const int half = blockIdx.z;
    const int n = p / 7, tp = p % 7;
    const int tq = (half == 0) ? tp + 1 : tp;
    const int tk = (half == 0) ? tp : tp + 1;
    const float* qb = q + ((size_t)(n * TT + tq) * LL + 1) * (HH * DD);
    const float* kb = k + ((size_t)(n * TT + tk) * LL + 1) * (HH * DD);

    const int tid = threadIdx.x;
    const int qi = tid >> 3, kg = tid & 7;
    const int q0 = qt * QT;

    float acc[25];
#pragma unroll
    for (int j = 0; j < 25; j++) acc[j] = 0.f;

    for (int h = 0; h < HH; h++) {
        __syncthreads();
        // load Q tile: 28 rows x 16 float4
#pragma unroll
        for (int it = 0; it < 2; it++) {
            int i = tid + it * K1_THREADS;
            int r = i >> 4, c = i & 15;
            float4 v = *(const float4*)(qb + ((size_t)(q0 + r) * HH + h) * DD + c * 4);
            *(float4*)(qs + r * ROWP + c * 4) = v;
        }
        // load K: 196 rows x 16 float4
#pragma unroll
        for (int it = 0; it < 14; it++) {
            int i = tid + it * K1_THREADS;
            int r = i >> 4, c = i & 15;
            float4 v = *(const float4*)(kb + ((size_t)r * HH + h) * DD + c * 4);
            *(float4*)(ks + r * ROWP + c * 4) = v;
        }
        __syncthreads();

        u64 s2[25];
#pragma unroll
        for (int j = 0; j < 25; j++) s2[j] = 0ull;

#pragma unroll 4
        for (int ds = 0; ds < 16; ds++) {
            ulonglong2 qv = *(const ulonglong2*)(qs + qi * ROWP + ds * 4);
#pragma unroll
            for (int j = 0; j < 25; j++) {
                ulonglong2 kv = *(const ulonglong2*)(ks + (kg + 8 * j) * ROWP + ds * 4);
                s2[j] = ffma2(qv.x, kv.x, s2[j]);
                s2[j] = ffma2(qv.y, kv.y, s2[j]);
            }
        }

        float s[25];
        float m = -1e30f;
#pragma unroll
        for (int j = 0; j < 25; j++) {
            int kk = kg + 8 * j;
            s[j] = (kk < LK) ? (lo2(s2[j]) + hi2(s2[j])) * 0.125f : -1e30f;
            m = fmaxf(m, s[j]);
        }
#pragma unroll
        for (int o = 4; o > 0; o >>= 1) m = fmaxf(m, __shfl_xor_sync(0xffffffffu, m, o));
        float sum = 0.f;
#pragma unroll
        for (int j = 0; j < 25; j++) { float e = __expf(s[j] - m); s[j] = e; sum += e; }
#pragma unroll
        for (int o = 4; o > 0; o >>= 1) sum += __shfl_xor_sync(0xffffffffu, sum, o);
        float inv = 1.0f / (12.0f * sum);
#pragma unroll
        for (int j = 0; j < 25; j++) acc[j] += s[j] * inv;
    }

    float* ob = g_attn + ((size_t)(half * LK + q0 + qi) * NPAIR + p) * LK;
#pragma unroll
    for (int j = 0; j < 25; j++) {
        int kk = kg + 8 * j;
        if (kk < LK) ob[kk] = acc[j];
    }
}

// ---------------------------------------------------------------------------
// Kernel 2: out[nt, q, c] = sum over k-cat(392) of A * Wgather
// grid (6 c-tiles, 196 q), 256 threads, 128x128 tile, 8x8 per thread (f32x2)
// ---------------------------------------------------------------------------
#define KT 28
#define K2_THREADS 256
#define MPAD 136

__global__ void __launch_bounds__(K2_THREADS) out_kernel(
    const float* __restrict__ w1, const float* __restrict__ w2,
    const int* __restrict__ idx, float* __restrict__ out)
{
    __shared__ float As[KT][MPAD];   // [k][m]
    __shared__ float Ws[KT][MPAD];   // [k][c]
    __shared__ int idxrow[LK];

    const int qq = blockIdx.y;
    const int c0 = blockIdx.x * 128;
    const int tid = threadIdx.x;
    const int tx = tid & 15, ty = tid >> 4;

    for (int i = tid; i < LK; i += K2_THREADS) idxrow[i] = idx[qq * LK + i];

    u64 acc2[8][4];
#pragma unroll
    for (int i = 0; i < 8; i++)
#pragma unroll
        for (int j = 0; j < 4; j++) acc2[i][j] = 0ull;

    for (int t = 0; t < 14; t++) {
        const int half = t / 7;
        const int kbase = (t % 7) * KT;
        const float* wsel = half ? w2 : w1;
        __syncthreads();   // also covers idxrow on first iteration

        // A tile: 128 m-rows x 28 k (float4 over k), transposed into As[k][m]
#pragma unroll
        for (int it = 0; it < 4; it++) {
            int i = tid + it * K2_THREADS;
            if (i < 896) {
                int mrow = i / 7, f = i % 7;
                int nn = mrow >> 3, tt = mrow & 7;
                float4 v = make_float4(0.f, 0.f, 0.f, 0.f);
                int pp; bool valid;
                if (half == 0) { valid = (tt >= 1); pp = nn * 7 + tt - 1; }
                else           { valid = (tt <= 6); pp = nn * 7 + tt; }
                if (valid)
                    v = *(const float4*)(g_attn +
                        ((size_t)(half * LK + qq) * NPAIR + pp) * LK + kbase + f * 4);
                As[f * 4 + 0][mrow] = v.x;
                As[f * 4 + 1][mrow] = v.y;
                As[f * 4 + 2][mrow] = v.z;
                As[f * 4 + 3][mrow] = v.w;
            }
        }
        // W tile: 28 k-rows x 128 c, gathered rows of w1/w2
#pragma unroll
        for (int it = 0; it < 4; it++) {
            int i = tid + it * K2_THREADS;
            if (i < 896) {
                int kk = i >> 5, f = i & 31;
                int r = idxrow[kbase + kk];
                float4 v = *(const float4*)(wsel + (size_t)r * CDIM + c0 + f * 4);
                *(float4*)(&Ws[kk][f * 4]) = v;
            }
        }
        __syncthreads();

#pragma unroll
        for (int kk = 0; kk < KT; kk++) {
            float4 a0 = *(const float4*)(&As[kk][ty * 8]);
            float4 a1 = *(const float4*)(&As[kk][ty * 8 + 4]);
            ulonglong2 b0 = *(const ulonglong2*)(&Ws[kk][tx * 8]);
            ulonglong2 b1 = *(const ulonglong2*)(&Ws[kk][tx * 8 + 4]);
            u64 ad0 = dup2(a0.x), ad1 = dup2(a0.y), ad2 = dup2(a0.z), ad3 = dup2(a0.w);
            u64 ad4 = dup2(a1.x), ad5 = dup2(a1.y), ad6 = dup2(a1.z), ad7 = dup2(a1.w);
            u64 bv[4] = { b0.x, b0.y, b1.x, b1.y };
            u64 ad[8] = { ad0, ad1, ad2, ad3, ad4, ad5, ad6, ad7 };
#pragma unroll
            for (int i = 0; i < 8; i++)
#pragma unroll
                for (int j = 0; j < 4; j++)
                    acc2[i][j] = ffma2(ad[i], bv[j], acc2[i][j]);
        }
    }

    // epilogue: out[n, t, q+1, c0 + tx*8 + 0..7]
#pragma unroll
    for (int i = 0; i < 8; i++) {
        int mrow = ty * 8 + i;
        int nn = mrow >> 3, tt = mrow & 7;
        float* ob = out + ((size_t)(nn * TT + tt) * LL + qq + 1) * CDIM + c0 + tx * 8;
        float4 v0 = make_float4(lo2(acc2[i][0]), hi2(acc2[i][0]),
                                lo2(acc2[i][1]), hi2(acc2[i][1]));
        float4 v1 = make_float4(lo2(acc2[i][2]), hi2(acc2[i][2]),
                                lo2(acc2[i][3]), hi2(acc2[i][3]));
        *(float4*)(ob) = v0;
        *(float4*)(ob + 4) = v1;
    }
}

// ---------------------------------------------------------------------------
// zero the l = 0 slice (output is poisoned by the harness)
// ---------------------------------------------------------------------------
__global__ void zero_l0_kernel(float* __restrict__ out) {
    int i = blockIdx.x * blockDim.x + threadIdx.x;   // 16*8*768 = 98304
    int nt = i / CDIM, c = i - nt * CDIM;
    out[(size_t)nt * LL * CDIM + c] = 0.f;
}

extern "C" void kernel_launch(void* const* d_in, const int* in_sizes, int n_in,
                              void* d_out, int out_size)
{
    const float* q  = (const float*)d_in[0];
    const float* k  = (const float*)d_in[1];
    const float* w1 = (const float*)d_in[2];
    const float* w2 = (const float*)d_in[3];
    const int*  idx = (const int*)d_in[4];
    float* out = (float*)d_out;

    cudaFuncSetAttribute(attn_kernel, cudaFuncAttributeMaxDynamicSharedMemorySize, SMEM1);

    attn_kernel<<<dim3(7, 112, 2), K1_THREADS, SMEM1>>>(q, k);
    zero_l0_kernel<<<96, 1024>>>(out);
    out_kernel<<<dim3(6, 196), K2_THREADS>>>(w1, w2, idx, out);
}

// round 3
// speedup vs baseline: 1.5321x; 1.5321x over previous
#include <cuda_runtime.h>
#include <cstdint>

typedef unsigned long long u64;

#define TT    8
#define LL    197
#define HH    12
#define DD    64
#define LK    196
#define NPAIR 112
#define CDIM  768

// attn scratch: [half][q][pair][k]  = 2*196*112*196 floats = 34.4 MB
__device__ float g_attn[2u * LK * NPAIR * LK];

// ---------------------------------------------------------------------------
// Kernel 1: tf32 tensor-core scores + softmax + mean over heads
// grid (2 qtiles, 112 pairs, 2 halves), 448 threads = 14 warps
// warp = (stripe 0..6 [m16 rows], nhalf 0..1 [13 or 12 n-tiles of 8])
// ---------------------------------------------------------------------------
#define K1_THREADS 448
#define QROWS 112
#define KROWS 200
#define PITCH 68

// smem layout (floats)
#define QS_OFF   0
#define KS_OFF   (2 * QROWS * PITCH)                 // 15232
#define RED_OFF  (KS_OFF + 2 * KROWS * PITCH)        // + 27200
#define REDSUM_OFF (RED_OFF + 2 * QROWS)
#define SMEM1_FLOATS (REDSUM_OFF + 2 * QROWS)
#define SMEM1_BYTES (SMEM1_FLOATS * 4)

__device__ __forceinline__ void cp16(uint32_t dst, const float* src) {
    asm volatile("cp.async.cg.shared.global [%0], [%1], 16;" :: "r"(dst), "l"(src));
}

__device__ __forceinline__ void split_tf32(float x, uint32_t& hi, uint32_t& lo) {
    uint32_t h;
    asm("cvt.rna.tf32.f32 %0, %1;" : "=r"(h) : "f"(x));
    float lf = x - __uint_as_float(h);
    uint32_t l;
    asm("cvt.rna.tf32.f32 %0, %1;" : "=r"(l) : "f"(lf));
    hi = h; lo = l;
}

__device__ __forceinline__ void mma_tf32(float* c,
    uint32_t a0, uint32_t a1, uint32_t a2, uint32_t a3,
    uint32_t b0, uint32_t b1)
{
    asm volatile("mma.sync.aligned.m16n8k8.row.col.f32.tf32.tf32.f32 "
        "{%0,%1,%2,%3},{%4,%5,%6,%7},{%8,%9},{%0,%1,%2,%3};"
        : "+f"(c[0]), "+f"(c[1]), "+f"(c[2]), "+f"(c[3])
        : "r"(a0), "r"(a1), "r"(a2), "r"(a3), "r"(b0), "r"(b1));
}

__device__ __forceinline__ void load_head(
    const float* __restrict__ q, const float* __restrict__ k,
    size_t qbase, size_t kbase, int q0, int tid, uint32_t smem_u32,
    int h, int buf)
{
    // Q: 112 rows x 16 float4
#pragma unroll
    for (int it = 0; it < 4; it++) {
        int i = tid + it * K1_THREADS;
        int row = i >> 4, c4 = i & 15;
        int qg = q0 + row; if (qg > 195) qg = 195;
        const float* src = q + qbase + (size_t)qg * (HH * DD) + h * DD + c4 * 4;
        uint32_t dst = smem_u32 + (uint32_t)(QS_OFF + (buf * QROWS + row) * PITCH + c4 * 4) * 4;
        cp16(dst, src);
    }
    // K: 200 rows x 16 float4
#pragma unroll
    for (int it = 0; it < 8; it++) {
        int i = tid + it * K1_THREADS;
        if (i < KROWS * 16) {
            int row = i >> 4, c4 = i & 15;
            int kg = row > 195 ? 195 : row;
            const float* src = k + kbase + (size_t)kg * (HH * DD) + h * DD + c4 * 4;
            uint32_t dst = smem_u32 + (uint32_t)(KS_OFF + (buf * KROWS + row) * PITCH + c4 * 4) * 4;
            cp16(dst, src);
        }
    }
    asm volatile("cp.async.commit_group;");
}

__global__ void __launch_bounds__(K1_THREADS, 1) attn_tc_kernel(
    const float* __restrict__ q, const float* __restrict__ k)
{
    extern __shared__ float sm[];
    const int tid = threadIdx.x;
    const int lane = tid & 31;
    const int wid = tid >> 5;
    const int stripe = wid >> 1;        // 0..6
    const int nhalf = wid & 1;          // n-half
    const int r0 = stripe * 16;
    const int qt = blockIdx.x;
    const int p = blockIdx.y;
    const int hf = blockIdx.z;
    const int n = p / 7, tp = p % 7;
    const int tq = (hf == 0) ? tp + 1 : tp;
    const int tk = (hf == 0) ? tp : tp + 1;
    const size_t qbase = ((size_t)(n * TT + tq) * LL + 1) * (HH * DD);
    const size_t kbase = ((size_t)(n * TT + tk) * LL + 1) * (HH * DD);
    const int q0 = qt * QROWS;

    uint32_t smem_u32;
    asm("{ .reg .u64 t; cvta.to.shared.u64 t, %1; cvt.u32.u64 %0, t; }"
        : "=r"(smem_u32) : "l"(sm));

    const int nt0 = nhalf ? 13 : 0;
    const int cnt = nhalf ? 12 : 13;
    const int rA = r0 + (lane >> 2);
    const int rB = rA + 8;

    float macc[13][4];
#pragma unroll
    for (int t = 0; t < 13; t++)
#pragma unroll
        for (int j = 0; j < 4; j++) macc[t][j] = 0.f;

    load_head(q, k, qbase, kbase, q0, tid, smem_u32, 0, 0);
    asm volatile("cp.async.wait_group 0;");
    __syncthreads();

    for (int h = 0; h < HH; h++) {
        const int buf = h & 1;
        if (h + 1 < HH) load_head(q, k, qbase, kbase, q0, tid, smem_u32, h + 1, buf ^ 1);

        const float* qs = sm + QS_OFF + buf * QROWS * PITCH;
        const float* ks = sm + KS_OFF + buf * KROWS * PITCH;

        float c[13][4];
#pragma unroll
        for (int t = 0; t < 13; t++)
#pragma unroll
            for (int j = 0; j < 4; j++) c[t][j] = 0.f;

#pragma unroll
        for (int kc = 0; kc < 8; kc++) {
            const int dcol = kc * 8 + (lane & 3);
            float a0f = qs[rA * PITCH + dcol];
            float a1f = qs[rB * PITCH + dcol];
            float a2f = qs[rA * PITCH + dcol + 4];
            float a3f = qs[rB * PITCH + dcol + 4];
            uint32_t ah0, al0, ah1, al1, ah2, al2, ah3, al3;
            split_tf32(a0f, ah0, al0);
            split_tf32(a1f, ah1, al1);
            split_tf32(a2f, ah2, al2);
            split_tf32(a3f, ah3, al3);
#pragma unroll
            for (int t = 0; t < 13; t++) {
                if (t < cnt) {
                    const int nt = nt0 + t;
                    const int brow = nt * 8 + (lane >> 2);
                    float b0f = ks[brow * PITCH + dcol];
                    float b1f = ks[brow * PITCH + dcol + 4];
                    uint32_t bh0, bl0, bh1, bl1;
                    split_tf32(b0f, bh0, bl0);
                    split_tf32(b1f, bh1, bl1);
                    mma_tf32(c[t], ah0, ah1, ah2, ah3, bh0, bh1);
                    mma_tf32(c[t], al0, al1, al2, al3, bh0, bh1);
                    mma_tf32(c[t], ah0, ah1, ah2, ah3, bl0, bl1);
                }
            }
        }

        // mask invalid n (cols 196..199 live in nt==24, local t==11, nhalf==1)
        if (nhalf && (lane & 3) >= 2) {
            c[11][0] = -1e30f; c[11][1] = -1e30f;
            c[11][2] = -1e30f; c[11][3] = -1e30f;
        }

        // row max (over this warp's n-half)
        float mA = -1e30f, mB = -1e30f;
#pragma unroll
        for (int t = 0; t < 13; t++) {
            if (t < cnt) {
                mA = fmaxf(mA, fmaxf(c[t][0], c[t][1]));
                mB = fmaxf(mB, fmaxf(c[t][2], c[t][3]));
            }
        }
#pragma unroll
        for (int o = 1; o <= 2; o <<= 1) {
            mA = fmaxf(mA, __shfl_xor_sync(0xffffffffu, mA, o));
            mB = fmaxf(mB, __shfl_xor_sync(0xffffffffu, mB, o));
        }
        if ((lane & 3) == 0) {
            sm[RED_OFF + rA * 2 + nhalf] = mA;
            sm[RED_OFF + rB * 2 + nhalf] = mB;
        }
        __syncthreads();
        mA = fmaxf(mA, sm[RED_OFF + rA * 2 + (1 - nhalf)]);
        mB = fmaxf(mB, sm[RED_OFF + rB * 2 + (1 - nhalf)]);

        // exp + row sum (scale 0.125 folded in)
        float sA = 0.f, sB = 0.f;
#pragma unroll
        for (int t = 0; t < 13; t++) {
            if (t < cnt) {
                c[t][0] = __expf((c[t][0] - mA) * 0.125f);
                c[t][1] = __expf((c[t][1] - mA) * 0.125f);
                c[t][2] = __expf((c[t][2] - mB) * 0.125f);
                c[t][3] = __expf((c[t][3] - mB) * 0.125f);
                sA += c[t][0] + c[t][1];
                sB += c[t][2] + c[t][3];
            }
        }
#pragma unroll
        for (int o = 1; o <= 2; o <<= 1) {
            sA += __shfl_xor_sync(0xffffffffu, sA, o);
            sB += __shfl_xor_sync(0xffffffffu, sB, o);
        }
        if ((lane & 3) == 0) {
            sm[REDSUM_OFF + rA * 2 + nhalf] = sA;
            sm[REDSUM_OFF + rB * 2 + nhalf] = sB;
        }
        __syncthreads();
        sA += sm[REDSUM_OFF + rA * 2 + (1 - nhalf)];
        sB += sm[REDSUM_OFF + rB * 2 + (1 - nhalf)];
        const float iA = 1.0f / (12.0f * sA);
        const float iB = 1.0f / (12.0f * sB);
#pragma unroll
        for (int t = 0; t < 13; t++) {
            if (t < cnt) {
                macc[t][0] += c[t][0] * iA;
                macc[t][1] += c[t][1] * iA;
                macc[t][2] += c[t][2] * iB;
                macc[t][3] += c[t][3] * iB;
            }
        }

        if (h + 1 < HH) asm volatile("cp.async.wait_group 0;");
        __syncthreads();
    }

    // stage mean through freed K smem, then coalesced store to g_attn
    float* stage = sm + KS_OFF;   // [112][196]
#pragma unroll
    for (int t = 0; t < 13; t++) {
        if (t < cnt) {
            const int col = (nt0 + t) * 8 + 2 * (lane & 3);
            if (col < 196)     stage[rA * 196 + col]     = macc[t][0];
            if (col + 1 < 196) stage[rA * 196 + col + 1] = macc[t][1];
            if (col < 196)     stage[rB * 196 + col]     = macc[t][2];
            if (col + 1 < 196) stage[rB * 196 + col + 1] = macc[t][3];
        }
    }
    __syncthreads();

    for (int i = tid; i < QROWS * 49; i += K1_THREADS) {
        int row = i / 49, f = i % 49;
        int qg = q0 + row;
        if (qg < 196) {
            float4 v = *(const float4*)(stage + row * 196 + f * 4);
            *(float4*)(g_attn + ((size_t)(hf * LK + qg) * NPAIR + p) * LK + f * 4) = v;
        }
    }
}

// ---------------------------------------------------------------------------
// Kernel 2: out[nt, q, c] = sum over k-cat(392) of A * Wgather  (unchanged)
// ---------------------------------------------------------------------------
__device__ __forceinline__ u64 ffma2(u64 a, u64 b, u64 c) {
    u64 d;
    asm("fma.rn.f32x2 %0, %1, %2, %3;" : "=l"(d) : "l"(a), "l"(b), "l"(c));
    return d;
}
__device__ __forceinline__ u64 dup2(float x) {
    u64 d;
    unsigned u = __float_as_uint(x);
    asm("mov.b64 %0, {%1, %1};" : "=l"(d) : "r"(u));
    return d;
}
__device__ __forceinline__ float lo2(u64 v) { return __uint_as_float((unsigned)v); }
__device__ __forceinline__ float hi2(u64 v) { return __uint_as_float((unsigned)(v >> 32)); }

#define KT 28
#define K2_THREADS 256
#define MPAD 136

__global__ void __launch_bounds__(K2_THREADS) out_kernel(
    const float* __restrict__ w1, const float* __restrict__ w2,
    const int* __restrict__ idx, float* __restrict__ out)
{
    __shared__ float As[KT][MPAD];
    __shared__ float Ws[KT][MPAD];
    __shared__ int idxrow[LK];

    const int qq = blockIdx.y;
    const int c0 = blockIdx.x * 128;
    const int tid = threadIdx.x;
    const int tx = tid & 15, ty = tid >> 4;

    for (int i = tid; i < LK; i += K2_THREADS) idxrow[i] = idx[qq * LK + i];

    u64 acc2[8][4];
#pragma unroll
    for (int i = 0; i < 8; i++)
#pragma unroll
        for (int j = 0; j < 4; j++) acc2[i][j] = 0ull;

    for (int t = 0; t < 14; t++) {
        const int half = t / 7;
        const int kbase = (t % 7) * KT;
        const float* wsel = half ? w2 : w1;
        __syncthreads();

#pragma unroll
        for (int it = 0; it < 4; it++) {
            int i = tid + it * K2_THREADS;
            if (i < 896) {
                int mrow = i / 7, f = i % 7;
                int nn = mrow >> 3, tt = mrow & 7;
                float4 v = make_float4(0.f, 0.f, 0.f, 0.f);
                int pp; bool valid;
                if (half == 0) { valid = (tt >= 1); pp = nn * 7 + tt - 1; }
                else           { valid = (tt <= 6); pp = nn * 7 + tt; }
                if (valid)
                    v = *(const float4*)(g_attn +
                        ((size_t)(half * LK + qq) * NPAIR + pp) * LK + kbase + f * 4);
                As[f * 4 + 0][mrow] = v.x;
                As[f * 4 + 1][mrow] = v.y;
                As[f * 4 + 2][mrow] = v.z;
                As[f * 4 + 3][mrow] = v.w;
            }
        }
#pragma unroll
        for (int it = 0; it < 4; it++) {
            int i = tid + it * K2_THREADS;
            if (i < 896) {
                int kk = i >> 5, f = i & 31;
                int r = idxrow[kbase + kk];
                float4 v = *(const float4*)(wsel + (size_t)r * CDIM + c0 + f * 4);
                *(float4*)(&Ws[kk][f * 4]) = v;
            }
        }
        __syncthreads();

#pragma unroll
        for (int kk = 0; kk < KT; kk++) {
            float4 a0 = *(const float4*)(&As[kk][ty * 8]);
            float4 a1 = *(const float4*)(&As[kk][ty * 8 + 4]);
            ulonglong2 b0 = *(const ulonglong2*)(&Ws[kk][tx * 8]);
            ulonglong2 b1 = *(const ulonglong2*)(&Ws[kk][tx * 8 + 4]);
            u64 ad[8] = { dup2(a0.x), dup2(a0.y), dup2(a0.z), dup2(a0.w),
                          dup2(a1.x), dup2(a1.y), dup2(a1.z), dup2(a1.w) };
            u64 bv[4] = { b0.x, b0.y, b1.x, b1.y };
#pragma unroll
            for (int i = 0; i < 8; i++)
#pragma unroll
                for (int j = 0; j < 4; j++)
                    acc2[i][j] = ffma2(ad[i], bv[j], acc2[i][j]);
        }
    }

#pragma unroll
    for (int i = 0; i < 8; i++) {
        int mrow = ty * 8 + i;
        int nn = mrow >> 3, tt = mrow & 7;
        float* ob = out + ((size_t)(nn * TT + tt) * LL + qq + 1) * CDIM + c0 + tx * 8;
        float4 v0 = make_float4(lo2(acc2[i][0]), hi2(acc2[i][0]),
                                lo2(acc2[i][1]), hi2(acc2[i][1]));
        float4 v1 = make_float4(lo2(acc2[i][2]), hi2(acc2[i][2]),
                                lo2(acc2[i][3]), hi2(acc2[i][3]));
        *(float4*)(ob) = v0;
        *(float4*)(ob + 4) = v1;
    }
}

__global__ void zero_l0_kernel(float* __restrict__ out) {
    int i = blockIdx.x * blockDim.x + threadIdx.x;
    int nt = i / CDIM, c = i - nt * CDIM;
    out[(size_t)nt * LL * CDIM + c] = 0.f;
}

extern "C" void kernel_launch(void* const* d_in, const int* in_sizes, int n_in,
                              void* d_out, int out_size)
{
    const float* q  = (const float*)d_in[0];
    const float* k  = (const float*)d_in[1];
    const float* w1 = (const float*)d_in[2];
    const float* w2 = (const float*)d_in[3];
    const int*  idx = (const int*)d_in[4];
    float* out = (float*)d_out;

    cudaFuncSetAttribute(attn_tc_kernel, cudaFuncAttributeMaxDynamicSharedMemorySize, SMEM1_BYTES);

    attn_tc_kernel<<<dim3(2, 112, 2), K1_THREADS, SMEM1_BYTES>>>(q, k);
    zero_l0_kernel<<<96, 1024>>>(out);
    out_kernel<<<dim3(6, 196), K2_THREADS>>>(w1, w2, idx, out);
}